// round 1
// baseline (speedup 1.0000x reference)
#include <cuda_runtime.h>
#include <math.h>

#define N_ENT   14541
#define EMB_DIM 768
#define TOP_K   1000
#define NEG_T   5
#define BS      128
#define MARGIN  0.5f

// Scratch (no cudaMalloc allowed)
__device__ float g_simi_mean[N_ENT];
__device__ float g_alpha[BS];

// ---------------------------------------------------------------------------
// Block reduce: valid result in thread 0. nthreads must be multiple of 32.
// ---------------------------------------------------------------------------
__device__ __forceinline__ float block_reduce_sum(float v, float* sh) {
    #pragma unroll
    for (int o = 16; o > 0; o >>= 1) v += __shfl_down_sync(0xffffffffu, v, o);
    int wid = threadIdx.x >> 5;
    int lid = threadIdx.x & 31;
    if (lid == 0) sh[wid] = v;
    __syncthreads();
    int nw = blockDim.x >> 5;
    if (wid == 0) {
        v = (lid < nw) ? sh[lid] : 0.0f;
        #pragma unroll
        for (int o = 16; o > 0; o >>= 1) v += __shfl_down_sync(0xffffffffu, v, o);
    }
    return v;
}

// ---------------------------------------------------------------------------
// Kernel 1: per-row mean of simi_score_mtx. One block per row. DRAM-bound.
// ---------------------------------------------------------------------------
__global__ void row_mean_kernel(const float* __restrict__ simi) {
    __shared__ float sh[8];
    const float* row = simi + (size_t)blockIdx.x * N_ENT;
    float s0 = 0.f, s1 = 0.f, s2 = 0.f, s3 = 0.f;
    int t = threadIdx.x;               // 256 threads
    int stride = blockDim.x;
    int c = t;
    // 4-way ILP accumulation
    for (; c + 3 * stride < N_ENT; c += 4 * stride) {
        s0 += row[c];
        s1 += row[c + stride];
        s2 += row[c + 2 * stride];
        s3 += row[c + 3 * stride];
    }
    for (; c < N_ENT; c += stride) s0 += row[c];
    float v = (s0 + s1) + (s2 + s3);
    v = block_reduce_sum(v, sh);
    if (threadIdx.x == 0) g_simi_mean[blockIdx.x] = v * (1.0f / (float)N_ENT);
}

// ---------------------------------------------------------------------------
// Kernel 2: per-sample alpha. One block (768 threads) per sample.
//   Phase A: thread d accumulates sum/sumsq of emb[idx[k]][d] over k (L2-bound
//            gathers; table fits L2). std(ddof=1) dotted with proj_w[0:768].
//   Phase B: strided over k: simi / |r-s| / r+s / s / r feature groups.
// ---------------------------------------------------------------------------
__global__ __launch_bounds__(EMB_DIM)
void alpha_kernel(const int*   __restrict__ ent_idx,
                  const float* __restrict__ stelp_scores,
                  const float* __restrict__ rotate_scores,
                  const float* __restrict__ emb,
                  const float* __restrict__ proj_w,
                  const float* __restrict__ proj_b) {
    __shared__ int   s_idx[TOP_K];
    __shared__ float sh[24];
    const int b   = blockIdx.x;
    const int tid = threadIdx.x;

    for (int k = tid; k < TOP_K; k += blockDim.x)
        s_idx[k] = ent_idx[b * TOP_K + k];
    __syncthreads();

    // ---- Phase A: embedding std over the top_k gathered rows ----
    const int d = tid;  // one dim per thread, 768 threads
    float s = 0.f, sq = 0.f;
    #pragma unroll 4
    for (int k = 0; k < TOP_K; k++) {
        float v = __ldg(emb + (size_t)s_idx[k] * EMB_DIM + d);
        s += v;
        sq = fmaf(v, v, sq);
    }
    float mean = s * (1.0f / (float)TOP_K);
    float var  = (sq - s * mean) * (1.0f / (float)(TOP_K - 1));
    var = fmaxf(var, 0.0f);
    float acc = sqrtf(var) * __ldg(proj_w + d);

    // ---- Phase B: simi + score feature groups ----
    const float* wS  = proj_w + EMB_DIM;                // simi
    const float* wD  = proj_w + EMB_DIM + TOP_K;        // |rot - stelp|
    const float* wA  = proj_w + EMB_DIM + 2 * TOP_K;    // stelp + rot
    const float* wSt = proj_w + EMB_DIM + 3 * TOP_K;    // stelp
    const float* wR  = proj_w + EMB_DIM + 4 * TOP_K;    // rot
    for (int k = tid; k < TOP_K; k += blockDim.x) {
        float ss = stelp_scores[b * TOP_K + k];
        float rr = rotate_scores[b * TOP_K + k];
        float sm = g_simi_mean[s_idx[k]];
        acc = fmaf(wS[k],  sm,            acc);
        acc = fmaf(wD[k],  fabsf(rr - ss), acc);
        acc = fmaf(wA[k],  ss + rr,       acc);
        acc = fmaf(wSt[k], ss,            acc);
        acc = fmaf(wR[k],  rr,            acc);
    }

    float total = block_reduce_sum(acc, sh);
    if (tid == 0) {
        float z = total + proj_b[0];
        g_alpha[b] = 1.0f / (1.0f + __expf(-z));
    }
}

// ---------------------------------------------------------------------------
// Kernel 3: margin ranking loss. Single block.
// ---------------------------------------------------------------------------
__global__ void loss_kernel(const float* __restrict__ pos_s,
                            const float* __restrict__ pos_r,
                            const float* __restrict__ neg_s,
                            const float* __restrict__ neg_r,
                            float* __restrict__ out) {
    __shared__ float sh[8];
    float acc = 0.f;
    for (int i = threadIdx.x; i < BS * NEG_T; i += blockDim.x) {
        int b = i / NEG_T;
        float a  = g_alpha[b];
        float pe = a * pos_s[b] + (1.0f - a) * pos_r[b];
        float ne = a * neg_s[i] + (1.0f - a) * neg_r[i];
        acc += fmaxf(MARGIN - pe + ne, 0.0f);
    }
    float total = block_reduce_sum(acc, sh);
    if (threadIdx.x == 0) out[0] = total * (1.0f / (float)(BS * NEG_T));
}

// ---------------------------------------------------------------------------
extern "C" void kernel_launch(void* const* d_in, const int* in_sizes, int n_in,
                              void* d_out, int out_size) {
    const float* pos_stelp  = (const float*)d_in[0];
    const float* pos_rotate = (const float*)d_in[1];
    const int*   ent_idx    = (const int*)  d_in[2];
    const float* neg_stelp  = (const float*)d_in[3];
    const float* neg_rotate = (const float*)d_in[4];
    const float* stelp_sc   = (const float*)d_in[5];
    const float* rotate_sc  = (const float*)d_in[6];
    const float* ent_emb    = (const float*)d_in[7];
    const float* simi_mtx   = (const float*)d_in[8];
    const float* proj_w     = (const float*)d_in[9];
    const float* proj_b     = (const float*)d_in[10];
    float* out = (float*)d_out;

    row_mean_kernel<<<N_ENT, 256>>>(simi_mtx);
    alpha_kernel<<<BS, EMB_DIM>>>(ent_idx, stelp_sc, rotate_sc,
                                  ent_emb, proj_w, proj_b);
    loss_kernel<<<1, 256>>>(pos_stelp, pos_rotate, neg_stelp, neg_rotate, out);
}

// round 2
// speedup vs baseline: 1.9719x; 1.9719x over previous
#include <cuda_runtime.h>
#include <math.h>

#define N_ENT   14541
#define EMB_DIM 768
#define EMB_V4  192            // EMB_DIM / 4
#define TOP_K   1000
#define NEG_T   5
#define BS      128
#define MARGIN  0.5f

// Scratch (no cudaMalloc allowed)
__device__ float g_simi_mean[N_ENT];
__device__ float g_alpha[BS];

// ---------------------------------------------------------------------------
// Block reduce: valid result in thread 0.
// ---------------------------------------------------------------------------
__device__ __forceinline__ float block_reduce_sum(float v, float* sh) {
    #pragma unroll
    for (int o = 16; o > 0; o >>= 1) v += __shfl_down_sync(0xffffffffu, v, o);
    int wid = threadIdx.x >> 5;
    int lid = threadIdx.x & 31;
    if (lid == 0) sh[wid] = v;
    __syncthreads();
    int nw = blockDim.x >> 5;
    if (wid == 0) {
        v = (lid < nw) ? sh[lid] : 0.0f;
        #pragma unroll
        for (int o = 16; o > 0; o >>= 1) v += __shfl_down_sync(0xffffffffu, v, o);
    }
    return v;
}

// ---------------------------------------------------------------------------
// Kernel 1: per-row mean of simi_score_mtx. One block per row.
// Rows are only 4B aligned (14541 % 4 = 1), so: scalar head to 16B alignment,
// float4 main loop (unrolled for MLP), scalar tail.
// ---------------------------------------------------------------------------
__global__ __launch_bounds__(256)
void row_mean_kernel(const float* __restrict__ simi) {
    __shared__ float sh[8];
    const int tid = threadIdx.x;
    const size_t e0 = (size_t)blockIdx.x * N_ENT;
    const size_t e1 = e0 + N_ENT;
    const size_t a0 = (e0 + 3) & ~(size_t)3;   // first 16B-aligned element
    const size_t a1 = e1 & ~(size_t)3;         // end of aligned region

    float s = 0.0f;
    // head (<=3 elements) + tail (<=3 elements), handled by low threads
    for (size_t e = e0 + tid; e < a0; e += 256) s += simi[e];
    for (size_t e = a1 + tid; e < e1; e += 256) s += simi[e];

    const float4* __restrict__ v4 = (const float4*)(simi + a0);
    const int nv = (int)((a1 - a0) >> 2);      // ~3634 or 3635
    float4 a = make_float4(0.f, 0.f, 0.f, 0.f);
    #pragma unroll 4
    for (int i = tid; i < nv; i += 256) {
        float4 x = v4[i];
        a.x += x.x; a.y += x.y; a.z += x.z; a.w += x.w;
    }
    s += (a.x + a.y) + (a.z + a.w);
    s = block_reduce_sum(s, sh);
    if (tid == 0) g_simi_mean[blockIdx.x] = s * (1.0f / (float)N_ENT);
}

// ---------------------------------------------------------------------------
// Kernel 2: per-sample alpha. One block (768 threads) per sample.
// Phase A: thread = (dim-group g in [0,192), k-slice j in [0,4)).
//   Each thread float4-gathers its 4 dims over k = j, j+4, ... (250 rows),
//   partials combined across the 4 k-slices via shared memory.
//   float4 on 16B boundaries within 32B-aligned rows -> 1 sector per load.
// Phase B: strided over k for the 5 score/simi feature groups.
// ---------------------------------------------------------------------------
__global__ __launch_bounds__(768)
void alpha_kernel(const int*   __restrict__ ent_idx,
                  const float* __restrict__ stelp_scores,
                  const float* __restrict__ rotate_scores,
                  const float* __restrict__ emb,
                  const float* __restrict__ proj_w,
                  const float* __restrict__ proj_b) {
    __shared__ int    s_idx[TOP_K];
    __shared__ float4 sh_sum[768];
    __shared__ float4 sh_sq[768];
    __shared__ float  sh[24];

    const int b   = blockIdx.x;
    const int tid = threadIdx.x;

    for (int k = tid; k < TOP_K; k += 768)
        s_idx[k] = ent_idx[b * TOP_K + k];
    __syncthreads();

    // ---- Phase A: gather + sum/sumsq, float4 per thread ----
    const int g = tid % EMB_V4;        // dim group: dims [4g, 4g+3]
    const int j = tid / EMB_V4;        // k-slice 0..3
    const float4* __restrict__ emb4 = (const float4*)emb;

    float4 s4 = make_float4(0.f, 0.f, 0.f, 0.f);
    float4 q4 = make_float4(0.f, 0.f, 0.f, 0.f);
    #pragma unroll 2
    for (int k = j; k < TOP_K; k += 4) {
        float4 v = __ldg(emb4 + (size_t)s_idx[k] * EMB_V4 + g);
        s4.x += v.x; s4.y += v.y; s4.z += v.z; s4.w += v.w;
        q4.x = fmaf(v.x, v.x, q4.x);
        q4.y = fmaf(v.y, v.y, q4.y);
        q4.z = fmaf(v.z, v.z, q4.z);
        q4.w = fmaf(v.w, v.w, q4.w);
    }
    sh_sum[tid] = s4;
    sh_sq[tid]  = q4;
    __syncthreads();

    float acc = 0.0f;
    if (tid < EMB_V4) {
        float4 S = sh_sum[tid];
        float4 Q = sh_sq[tid];
        #pragma unroll
        for (int jj = 1; jj < 4; jj++) {
            float4 s2 = sh_sum[jj * EMB_V4 + tid];
            float4 q2 = sh_sq[jj * EMB_V4 + tid];
            S.x += s2.x; S.y += s2.y; S.z += s2.z; S.w += s2.w;
            Q.x += q2.x; Q.y += q2.y; Q.z += q2.z; Q.w += q2.w;
        }
        const float invK  = 1.0f / (float)TOP_K;
        const float invK1 = 1.0f / (float)(TOP_K - 1);
        float sums[4] = {S.x, S.y, S.z, S.w};
        float sqs[4]  = {Q.x, Q.y, Q.z, Q.w};
        #pragma unroll
        for (int c = 0; c < 4; c++) {
            float mean = sums[c] * invK;
            float var  = (sqs[c] - sums[c] * mean) * invK1;
            var = fmaxf(var, 0.0f);
            acc = fmaf(sqrtf(var), __ldg(proj_w + tid * 4 + c), acc);
        }
    }

    // ---- Phase B: simi + score feature groups ----
    const float* wS  = proj_w + EMB_DIM;                // simi
    const float* wD  = proj_w + EMB_DIM + TOP_K;        // |rot - stelp|
    const float* wA  = proj_w + EMB_DIM + 2 * TOP_K;    // stelp + rot
    const float* wSt = proj_w + EMB_DIM + 3 * TOP_K;    // stelp
    const float* wR  = proj_w + EMB_DIM + 4 * TOP_K;    // rot
    for (int k = tid; k < TOP_K; k += 768) {
        float ss = stelp_scores[b * TOP_K + k];
        float rr = rotate_scores[b * TOP_K + k];
        float sm = g_simi_mean[s_idx[k]];
        acc = fmaf(wS[k],  sm,             acc);
        acc = fmaf(wD[k],  fabsf(rr - ss), acc);
        acc = fmaf(wA[k],  ss + rr,        acc);
        acc = fmaf(wSt[k], ss,             acc);
        acc = fmaf(wR[k],  rr,             acc);
    }

    float total = block_reduce_sum(acc, sh);
    if (tid == 0) {
        float z = total + proj_b[0];
        g_alpha[b] = 1.0f / (1.0f + __expf(-z));
    }
}

// ---------------------------------------------------------------------------
// Kernel 3: margin ranking loss. Single block.
// ---------------------------------------------------------------------------
__global__ void loss_kernel(const float* __restrict__ pos_s,
                            const float* __restrict__ pos_r,
                            const float* __restrict__ neg_s,
                            const float* __restrict__ neg_r,
                            float* __restrict__ out) {
    __shared__ float sh[8];
    float acc = 0.f;
    for (int i = threadIdx.x; i < BS * NEG_T; i += blockDim.x) {
        int b = i / NEG_T;
        float a  = g_alpha[b];
        float pe = a * pos_s[b] + (1.0f - a) * pos_r[b];
        float ne = a * neg_s[i] + (1.0f - a) * neg_r[i];
        acc += fmaxf(MARGIN - pe + ne, 0.0f);
    }
    float total = block_reduce_sum(acc, sh);
    if (threadIdx.x == 0) out[0] = total * (1.0f / (float)(BS * NEG_T));
}

// ---------------------------------------------------------------------------
extern "C" void kernel_launch(void* const* d_in, const int* in_sizes, int n_in,
                              void* d_out, int out_size) {
    const float* pos_stelp  = (const float*)d_in[0];
    const float* pos_rotate = (const float*)d_in[1];
    const int*   ent_idx    = (const int*)  d_in[2];
    const float* neg_stelp  = (const float*)d_in[3];
    const float* neg_rotate = (const float*)d_in[4];
    const float* stelp_sc   = (const float*)d_in[5];
    const float* rotate_sc  = (const float*)d_in[6];
    const float* ent_emb    = (const float*)d_in[7];
    const float* simi_mtx   = (const float*)d_in[8];
    const float* proj_w     = (const float*)d_in[9];
    const float* proj_b     = (const float*)d_in[10];
    float* out = (float*)d_out;

    row_mean_kernel<<<N_ENT, 256>>>(simi_mtx);
    alpha_kernel<<<BS, 768>>>(ent_idx, stelp_sc, rotate_sc,
                              ent_emb, proj_w, proj_b);
    loss_kernel<<<1, 256>>>(pos_stelp, pos_rotate, neg_stelp, neg_rotate, out);
}